// round 7
// baseline (speedup 1.0000x reference)
#include <cuda_runtime.h>

#define NS   48000
#define NIN  400
#define NSEG 401      // head(60) + 399 interior(120) + tail(60)
#define NB   16
#define NM   64
#define NROWS (NB*NM)

// Scratch (allocation-free)
__device__ float2 g_Bp[(size_t)NROWS * NSEG];  // per-(row,seg) phase base {radians, turns}, pre-reduced
__device__ double g_FT[NSEG];                  // per-segment frac totals (for scan)
__device__ float4 g_F1q[NSEG * 30];            // shared frac-cumsum table (float4-packed, 120/seg)

// Exact replica of the reference's fp32 position/frac computation.
__device__ __forceinline__ float ref_frac(int j) {
    const float SCALE = 400.0f / 48000.0f;   // fl32(1/120)
    float pos = __fsub_rn(__fmul_rn(__fadd_rn((float)j, 0.5f), SCALE), 0.5f);
    pos = fminf(fmaxf(pos, 0.0f), 399.0f);
    float fi = floorf(pos);
    return __fsub_rn(pos, fi);               // exact (Sterbenz)
}

// Kernel A: row-independent cumulative-frac table. One WARP per segment,
// lane handles 4 contiguous samples: local serial scan + one dbl-shfl warp
// scan of lane totals. No __syncthreads, float4 stores.
__global__ void __launch_bounds__(256) f1_kernel() {
    int w = threadIdx.x >> 5, lane = threadIdx.x & 31;
    int s = blockIdx.x * 8 + w;
    if (s >= NSEG) return;
    int start = (s == 0) ? 0 : 60 + (s - 1) * 120;

    int m0 = lane * 4;
    double s0 = (double)ref_frac(start + m0);
    double s1 = s0 + (double)ref_frac(start + m0 + 1);
    double s2 = s1 + (double)ref_frac(start + m0 + 2);
    double s3 = s2 + (double)ref_frac(start + m0 + 3);

    // warp inclusive scan of lane totals, then exclusive
    double T = s3, inc = T;
    #pragma unroll
    for (int off = 1; off < 32; off <<= 1) {
        double n = __shfl_up_sync(0xFFFFFFFFu, inc, off);
        if (lane >= off) inc += n;
    }
    double base = inc - T;    // exclusive prefix of lane totals

    if (m0 < 120) {           // lanes 0..29 hold samples 0..119
        g_F1q[s * 30 + lane] = make_float4((float)(base + s0), (float)(base + s1),
                                           (float)(base + s2), (float)(base + s3));
    }
    // FT[s] = sum of fracs over samples 0..119 = exclusive prefix at lane 30.
    // (Only read for interior segments, where cnt==120.)
    if (lane == 30) g_FT[s] = base;
}

// Kernel B: per-row exclusive prefix over segment sums (fp64, shuffle-based),
// then fold in phase[row][0] and reduce mod 2pi ONCE here, storing the base
// as {radians, turns} floats so synth setup is pure fp32.
__global__ void __launch_bounds__(512) scan_kernel(const float* __restrict__ params) {
    int r = blockIdx.x;                 // 0..1023 : b*64 + mode
    int b = r >> 6, mode = r & 63;
    const float* F = params + (size_t)(b * 192 + mode) * 400;  // channel 0 = freqs
    const float* P = F + 128 * 400;                            // channel 2 = phase
    int t = threadIdx.x;

    double v = 0.0;
    if (t == 0) {
        v = 60.0 * (double)F[0];        // head: frac == 0 for all 60 samples
    } else if (t <= 399) {
        int i = t - 1;
        double f0 = F[i], f1 = F[i + 1];
        v = 120.0 * f0 + (f1 - f0) * g_FT[t];
    }

    int lane = t & 31, w = t >> 5;
    double sv = v;
    #pragma unroll
    for (int off = 1; off < 32; off <<= 1) {
        double n = __shfl_up_sync(0xFFFFFFFFu, sv, off);
        if (lane >= off) sv += n;
    }
    __shared__ double wsum[16];
    if (lane == 31) wsum[w] = sv;
    __syncthreads();
    if (w == 0) {
        double x = (lane < 16) ? wsum[lane] : 0.0;
        #pragma unroll
        for (int off = 1; off < 16; off <<= 1) {
            double n = __shfl_up_sync(0xFFFFFFFFu, x, off);
            if (lane >= off) x += n;
        }
        if (lane < 16) wsum[lane] = x;
    }
    __syncthreads();
    if (t <= 400) {
        double excl = sv + ((w > 0) ? wsum[w - 1] : 0.0) - v;
        double tot  = excl + (double)P[0];
        double tt   = tot * 0.15915494309189535;     // turns
        double kk   = rint(tt);
        double ft   = tt - kk;                       // [-0.5, 0.5] turns
        g_Bp[(size_t)r * NSEG + t] =
            make_float2((float)(ft * 6.283185307179586), (float)ft);
    }
}

// Kernel C: synthesis. Block=(segment s, batch b), 64 threads, 2 samples/thread.
// MUFU.SIN rt ~16 cyc/warp/SMSP (empirical): hybrid sin — 1/5 of modes via
// fma-pipe polynomial (turns phase, magic-rint reduce, deg-11 odd minimax in
// radians), 4/5 via MUFU. Setup is pure fp32 now (base pre-reduced in scan).
__global__ void __launch_bounds__(64) synth_kernel(const float* __restrict__ params,
                                                   float* __restrict__ out) {
    int s = blockIdx.x, b = blockIdx.y;
    __shared__ float4 md0[64];   // {base_rad, f0_rad, dF_rad, a0}
    __shared__ float4 md1[64];   // {base_trn, f0_trn, dF_trn, da}
    int tid = threadIdx.x;

    {
        int mode = tid;          // 64 threads == 64 modes
        const float* F = params + (size_t)(b * 192 + mode) * 400;
        const float* A = F + 64 * 400;      // channel 1 = amps
        int i  = (s == 0) ? 0 : ((s <= 399) ? s - 1 : 399);
        int i1 = min(i + 1, 399);
        float f0 = F[i];
        float dw = F[i1] - f0;
        float a0 = A[i];
        float da = A[i1] - a0;
        float2 bp = g_Bp[(size_t)(b * 64 + mode) * NSEG + s];
        const float INV2PI_F = 0.15915494f;
        md0[mode] = make_float4(bp.x, f0, dw, a0);
        md1[mode] = make_float4(bp.y, f0 * INV2PI_F, dw * INV2PI_F, da);
    }
    __syncthreads();

    int m = tid;
    if (m >= 60) return;                    // 60 threads x 2 samples = 120
    bool interior = (s != 0 && s != 400);
    int start = (s == 0) ? 0 : 60 + (s - 1) * 120;
    int j0 = start + m;
    int j1 = start + m + 60;

    const float* F1 = (const float*)g_F1q;
    float t1a = (float)(m + 1),  t1b = (float)(m + 61);
    float F1a = F1[s * 120 + m], F1b = F1[s * 120 + m + 60];
    float fra = ref_frac(j0);
    float frb = interior ? ref_frac(j1) : 0.0f;

    const float MAGIC  = 12582912.0f;       // 1.5 * 2^23
    const float TWOPI  = 6.2831853f;
    const float C11 = -2.3889859e-08f;
    const float C9  =  2.7525562e-06f;
    const float C7  = -0.00019840874f;
    const float C5  =  0.0083333310f;
    const float C3  = -0.16666667f;

    float acc_a = 0.0f, acc_b = 0.0f;
#pragma unroll
    for (int k = 0; k < 64; k++) {
        if (k % 5 == 0) {
            // fma-pipe path (13 of 64 modes): turns + magic reduce + poly
            float4 q = md1[k];
            float a0k = md0[k].w, dak = q.w;
            float ph = fmaf(t1a, q.y, q.x); ph = fmaf(F1a, q.z, ph);
            float kr = (ph + MAGIC) - MAGIC;        // rint(ph) in turns
            float r  = (ph - kr) * TWOPI;           // [-pi, pi] radians
            float x2 = r * r;
            float p  = fmaf(C11, x2, C9);
            p = fmaf(p, x2, C7); p = fmaf(p, x2, C5);
            p = fmaf(p, x2, C3); p = fmaf(p, x2, 1.0f);
            float aa = fmaf(dak, fra, a0k);
            acc_a = fmaf(aa * r, p, acc_a);
            float phb = fmaf(t1b, q.y, q.x); phb = fmaf(F1b, q.z, phb);
            float krb = (phb + MAGIC) - MAGIC;
            float rb  = (phb - krb) * TWOPI;
            float xb2 = rb * rb;
            float pb  = fmaf(C11, xb2, C9);
            pb = fmaf(pb, xb2, C7); pb = fmaf(pb, xb2, C5);
            pb = fmaf(pb, xb2, C3); pb = fmaf(pb, xb2, 1.0f);
            float ab = fmaf(dak, frb, a0k);
            acc_b = fmaf(ab * rb, pb, acc_b);
        } else {
            // MUFU path (51 of 64 modes)
            float4 q = md0[k];
            float dak = md1[k].w;
            float ph  = fmaf(t1a, q.y, q.x); ph  = fmaf(F1a, q.z, ph);
            float phb = fmaf(t1b, q.y, q.x); phb = fmaf(F1b, q.z, phb);
            float aa = fmaf(dak, fra, q.w);
            float ab = fmaf(dak, frb, q.w);
            acc_a = fmaf(aa, __sinf(ph),  acc_a);
            acc_b = fmaf(ab, __sinf(phb), acc_b);
        }
    }

    out[(size_t)b * NS + j0] = acc_a;
    if (interior) out[(size_t)b * NS + j1] = acc_b;
}

extern "C" void kernel_launch(void* const* d_in, const int* in_sizes, int n_in,
                              void* d_out, int out_size) {
    const float* params = (const float*)d_in[0];
    float* out = (float*)d_out;
    f1_kernel<<<(NSEG + 7) / 8, 256>>>();
    scan_kernel<<<NROWS, 512>>>(params);
    dim3 grid(NSEG, NB);
    synth_kernel<<<grid, 64>>>(params, out);
}